// round 13
// baseline (speedup 1.0000x reference)
#include <cuda_runtime.h>

// ContrastivePredictionLoss — two-kernel, R13: block-granularity sweep point 3.
// Measured stage-A curve: 1024 blocks -> 34.7us, 2048 -> 31.1us. This round:
// 4096 blocks (64/batch, 4 float4-triples per thread) — halves per-block
// runtime and grid drain tail, doubles scheduler slack for DRAM-latency
// backfill. Streaming loop body keeps the (neutral-but-harmless) 2-deep
// software pipeline. Finalize: R6 structure adapted to 4096 partials.

#define NB 64
#define ELEMS_PER_BATCH (4 * 256 * 256)      // 262144
#define BLOCKS_PER_BATCH 64
#define NBLOCKS (NB * BLOCKS_PER_BATCH)      // 4096
#define THREADS_A 256
#define ELEMS_PER_BLOCK (ELEMS_PER_BATCH / BLOCKS_PER_BATCH)   // 4096
#define VECS_PER_BLOCK (ELEMS_PER_BLOCK / 4)                   // 1024 float4
#define VECS_PER_THREAD (VECS_PER_BLOCK / THREADS_A)           // 4

// Scratch (allocation-free __device__ globals).
__device__ float g_part_err[NBLOCKS];
__device__ float g_part_unc[NBLOCKS];

__global__ __launch_bounds__(THREADS_A)
void cpl_reduce_kernel(const float4* __restrict__ pm,
                       const float4* __restrict__ ps,
                       const float4* __restrict__ tg) {
    const int blk = blockIdx.x;                      // b * 64 + chunk
    const int tid = threadIdx.x;
    const long base = (long)blk * VECS_PER_BLOCK + tid;

    float se = 0.0f;   // sum |pm - tg|
    float su = 0.0f;   // sum ps

    // 2-deep software pipeline.
    float4 m0 = pm[base];
    float4 t0 = tg[base];
    float4 s0 = ps[base];

    #pragma unroll
    for (int i = 1; i < VECS_PER_THREAD; i++) {
        const long idx = base + (long)i * THREADS_A;
        float4 m1 = pm[idx];
        float4 t1 = tg[idx];
        float4 s1 = ps[idx];

        se += fabsf(m0.x - t0.x) + fabsf(m0.y - t0.y)
            + fabsf(m0.z - t0.z) + fabsf(m0.w - t0.w);
        su += s0.x + s0.y + s0.z + s0.w;

        m0 = m1; t0 = t1; s0 = s1;
    }
    se += fabsf(m0.x - t0.x) + fabsf(m0.y - t0.y)
        + fabsf(m0.z - t0.z) + fabsf(m0.w - t0.w);
    su += s0.x + s0.y + s0.z + s0.w;

    // Warp reduce (deterministic shuffle tree)
    #pragma unroll
    for (int off = 16; off > 0; off >>= 1) {
        se += __shfl_down_sync(0xFFFFFFFFu, se, off);
        su += __shfl_down_sync(0xFFFFFFFFu, su, off);
    }

    __shared__ float s_se[THREADS_A / 32];
    __shared__ float s_su[THREADS_A / 32];
    const int wid = tid >> 5;
    const int lid = tid & 31;
    if (lid == 0) { s_se[wid] = se; s_su[wid] = su; }
    __syncthreads();

    if (wid == 0) {
        se = (lid < THREADS_A / 32) ? s_se[lid] : 0.0f;
        su = (lid < THREADS_A / 32) ? s_su[lid] : 0.0f;
        #pragma unroll
        for (int off = 4; off > 0; off >>= 1) {
            se += __shfl_down_sync(0xFFFFFFFFu, se, off);
            su += __shfl_down_sync(0xFFFFFFFFu, su, off);
        }
        if (lid == 0) {
            g_part_err[blk] = se;
            g_part_unc[blk] = su;
        }
    }
}

#define THREADS_B 256

__global__ __launch_bounds__(THREADS_B)
void cpl_finalize_kernel(float* __restrict__ out) {
    const int tid = threadIdx.x;
    const int wid = tid >> 5;
    const int lid = tid & 31;

    // 4096 floats per array = 1024 float4. Batch b occupies float4 indices
    // [b*16, b*16+16). Thread -> b = tid>>2, quarter q = tid&3: 4 float4 of
    // err + 4 float4 of unc, all independent loads.
    const int b = tid >> 2;
    const int q = tid & 3;
    const float4* pe4 = (const float4*)g_part_err;
    const float4* pu4 = (const float4*)g_part_unc;

    float pe = 0.0f, pu = 0.0f;
    #pragma unroll
    for (int k = 0; k < 4; k++) {
        float4 e = pe4[b * 16 + q * 4 + k];
        float4 u = pu4[b * 16 + q * 4 + k];
        pe += (e.x + e.y) + (e.z + e.w);
        pu += (u.x + u.y) + (u.z + u.w);
    }

    __shared__ float s_pe[4][NB];
    __shared__ float s_pu[4][NB];
    s_pe[q][b] = pe;
    s_pu[q][b] = pu;
    __syncthreads();

    __shared__ float errs[NB];
    __shared__ float uncs[NB];
    if (tid < NB) {
        const float inv = 1.0f / (float)ELEMS_PER_BATCH;
        errs[tid] = ((s_pe[0][tid] + s_pe[1][tid]) + (s_pe[2][tid] + s_pe[3][tid])) * inv;
        uncs[tid] = ((s_pu[0][tid] + s_pu[1][tid]) + (s_pu[2][tid] + s_pu[3][tid])) * inv;
    }
    __syncthreads();

    // Pairwise hinge over upper triangle (i < j), fixed iteration order.
    float acc = 0.0f;
    #pragma unroll
    for (int p = tid; p < NB * NB; p += THREADS_B) {
        const int i = p >> 6;
        const int j = p & 63;
        if (i < j) {
            const float d = ((errs[i] > errs[j]) ? (uncs[j] - uncs[i])
                                                 : (uncs[i] - uncs[j])) + 1.0f;
            acc += fmaxf(d, 0.0f);
        }
    }

    #pragma unroll
    for (int off = 16; off > 0; off >>= 1)
        acc += __shfl_down_sync(0xFFFFFFFFu, acc, off);

    __shared__ float s_acc[THREADS_B / 32];
    if (lid == 0) s_acc[wid] = acc;
    __syncthreads();

    if (tid == 0) {
        float total = 0.0f;
        #pragma unroll
        for (int w = 0; w < THREADS_B / 32; w++) total += s_acc[w];
        const int num_pairs = NB * (NB - 1) / 2;   // 2016
        out[0] = total / (float)num_pairs;
    }
}

extern "C" void kernel_launch(void* const* d_in, const int* in_sizes, int n_in,
                              void* d_out, int out_size) {
    const float4* pm = (const float4*)d_in[0];   // pred_mean
    const float4* ps = (const float4*)d_in[1];   // pred_std
    const float4* tg = (const float4*)d_in[2];   // targets
    float* out = (float*)d_out;

    cpl_reduce_kernel<<<NBLOCKS, THREADS_A>>>(pm, ps, tg);
    cpl_finalize_kernel<<<1, THREADS_B>>>(out);
}

// round 14
// speedup vs baseline: 1.0087x; 1.0087x over previous
#include <cuda_runtime.h>

// ContrastivePredictionLoss — two-kernel, R14.
// Stage A: 4096-block grid KEPT (block-granularity sweep: 1024->34.7us,
//          2048->31.0us, 4096->29.8us measured) with 2-deep pipeline body.
// Stage B: widened finalize — 1024 threads, ONE float4 load per array per
//          thread (single memory-latency round instead of R13's 8 serialized
//          loads/thread), 16-lane shuffle reduction, hinge over 1024 threads.

#define NB 64
#define ELEMS_PER_BATCH (4 * 256 * 256)      // 262144
#define BLOCKS_PER_BATCH 64
#define NBLOCKS (NB * BLOCKS_PER_BATCH)      // 4096
#define THREADS_A 256
#define ELEMS_PER_BLOCK (ELEMS_PER_BATCH / BLOCKS_PER_BATCH)   // 4096
#define VECS_PER_BLOCK (ELEMS_PER_BLOCK / 4)                   // 1024 float4
#define VECS_PER_THREAD (VECS_PER_BLOCK / THREADS_A)           // 4

// Scratch (allocation-free __device__ globals).
__device__ float g_part_err[NBLOCKS];
__device__ float g_part_unc[NBLOCKS];

__global__ __launch_bounds__(THREADS_A)
void cpl_reduce_kernel(const float4* __restrict__ pm,
                       const float4* __restrict__ ps,
                       const float4* __restrict__ tg) {
    const int blk = blockIdx.x;                      // b * 64 + chunk
    const int tid = threadIdx.x;
    const long base = (long)blk * VECS_PER_BLOCK + tid;

    float se = 0.0f;   // sum |pm - tg|
    float su = 0.0f;   // sum ps

    // 2-deep software pipeline.
    float4 m0 = pm[base];
    float4 t0 = tg[base];
    float4 s0 = ps[base];

    #pragma unroll
    for (int i = 1; i < VECS_PER_THREAD; i++) {
        const long idx = base + (long)i * THREADS_A;
        float4 m1 = pm[idx];
        float4 t1 = tg[idx];
        float4 s1 = ps[idx];

        se += fabsf(m0.x - t0.x) + fabsf(m0.y - t0.y)
            + fabsf(m0.z - t0.z) + fabsf(m0.w - t0.w);
        su += s0.x + s0.y + s0.z + s0.w;

        m0 = m1; t0 = t1; s0 = s1;
    }
    se += fabsf(m0.x - t0.x) + fabsf(m0.y - t0.y)
        + fabsf(m0.z - t0.z) + fabsf(m0.w - t0.w);
    su += s0.x + s0.y + s0.z + s0.w;

    // Warp reduce (deterministic shuffle tree)
    #pragma unroll
    for (int off = 16; off > 0; off >>= 1) {
        se += __shfl_down_sync(0xFFFFFFFFu, se, off);
        su += __shfl_down_sync(0xFFFFFFFFu, su, off);
    }

    __shared__ float s_se[THREADS_A / 32];
    __shared__ float s_su[THREADS_A / 32];
    const int wid = tid >> 5;
    const int lid = tid & 31;
    if (lid == 0) { s_se[wid] = se; s_su[wid] = su; }
    __syncthreads();

    if (wid == 0) {
        se = (lid < THREADS_A / 32) ? s_se[lid] : 0.0f;
        su = (lid < THREADS_A / 32) ? s_su[lid] : 0.0f;
        #pragma unroll
        for (int off = 4; off > 0; off >>= 1) {
            se += __shfl_down_sync(0xFFFFFFFFu, se, off);
            su += __shfl_down_sync(0xFFFFFFFFu, su, off);
        }
        if (lid == 0) {
            g_part_err[blk] = se;
            g_part_unc[blk] = su;
        }
    }
}

#define THREADS_B 1024

__global__ __launch_bounds__(THREADS_B)
void cpl_finalize_kernel(float* __restrict__ out) {
    const int tid = threadIdx.x;
    const int wid = tid >> 5;
    const int lid = tid & 31;

    // 4096 floats per array = 1024 float4; batch b owns float4 [b*16, b*16+16).
    // Thread (b = tid>>4, q = tid&15): ONE float4 from each array — all 2048
    // loads issue in a single latency round.
    const int b = tid >> 4;
    const int q = tid & 15;
    const float4* pe4 = (const float4*)g_part_err;
    const float4* pu4 = (const float4*)g_part_unc;

    float4 e = pe4[b * 16 + q];
    float4 u = pu4[b * 16 + q];
    float pe = (e.x + e.y) + (e.z + e.w);
    float pu = (u.x + u.y) + (u.z + u.w);

    // Reduce across the 16 lanes that share a batch (contiguous within a warp).
    #pragma unroll
    for (int off = 8; off > 0; off >>= 1) {
        pe += __shfl_down_sync(0xFFFFFFFFu, pe, off);
        pu += __shfl_down_sync(0xFFFFFFFFu, pu, off);
    }

    __shared__ float errs[NB];
    __shared__ float uncs[NB];
    if (q == 0) {
        const float inv = 1.0f / (float)ELEMS_PER_BATCH;
        errs[b] = pe * inv;
        uncs[b] = pu * inv;
    }
    __syncthreads();

    // Pairwise hinge over upper triangle (i < j), fixed iteration order.
    float acc = 0.0f;
    #pragma unroll
    for (int p = tid; p < NB * NB; p += THREADS_B) {
        const int i = p >> 6;
        const int j = p & 63;
        if (i < j) {
            const float d = ((errs[i] > errs[j]) ? (uncs[j] - uncs[i])
                                                 : (uncs[i] - uncs[j])) + 1.0f;
            acc += fmaxf(d, 0.0f);
        }
    }

    #pragma unroll
    for (int off = 16; off > 0; off >>= 1)
        acc += __shfl_down_sync(0xFFFFFFFFu, acc, off);

    __shared__ float s_acc[THREADS_B / 32];
    if (lid == 0) s_acc[wid] = acc;
    __syncthreads();

    if (tid == 0) {
        float total = 0.0f;
        #pragma unroll
        for (int w = 0; w < THREADS_B / 32; w++) total += s_acc[w];
        const int num_pairs = NB * (NB - 1) / 2;   // 2016
        out[0] = total / (float)num_pairs;
    }
}

extern "C" void kernel_launch(void* const* d_in, const int* in_sizes, int n_in,
                              void* d_out, int out_size) {
    const float4* pm = (const float4*)d_in[0];   // pred_mean
    const float4* ps = (const float4*)d_in[1];   // pred_std
    const float4* tg = (const float4*)d_in[2];   // targets
    float* out = (float*)d_out;

    cpl_reduce_kernel<<<NBLOCKS, THREADS_A>>>(pm, ps, tg);
    cpl_finalize_kernel<<<1, THREADS_B>>>(out);
}